// round 16
// baseline (speedup 1.0000x reference)
#include <cuda_runtime.h>
#include <cuda_bf16.h>
#include <cstdint>
#include <math.h>

#define P     48
#define FLEN  168
#define HIST  336
#define HOFF  288
#define NCT   21      // col-tiles of 8
#define NBS   3       // b-frag k-steps (Gh, K=48)

__device__ __align__(16) uint32_t g_Bfrag[NCT * NBS * 32 * 2];   // 16128 B
__device__ __align__(16) float g_C[FLEN];
__device__ float g_lv;

typedef unsigned long long ull;

// ---------------------------------------------------------------------------
// Kernel 1: precompute (512 threads): 48 sequential AR steps, then log-step
// composition for t in [48,168), then C/lv/b-frag emission (Gh only).
// ---------------------------------------------------------------------------
__global__ void precompute_kernel(const float* __restrict__ phi,
                                  const float* __restrict__ bias,
                                  const float* __restrict__ log_sigma2,
                                  const float* __restrict__ mu_p,
                                  const float* __restrict__ sigma_p) {
    __shared__ float h[P + 1][221];
    const int tid = threadIdx.x;

    if (tid <= P) {
        const int k = tid;
        float ph[P];
#pragma unroll
        for (int j = 0; j < P; j++) ph[j] = phi[j];
#pragma unroll
        for (int i = 0; i < P; i++) h[k][i] = (k == i) ? 1.0f : 0.0f;
        const float b0 = (k == P) ? bias[0] : 0.0f;
        float pw[8];
#pragma unroll
        for (int i = 0; i < 8; i++) pw[i] = h[k][40 + i];
#pragma unroll 1
        for (int t = 0; t < P; t++) {
            float s0 = 0.f, s1 = 0.f, s2 = 0.f, s3 = 0.f;
#pragma unroll
            for (int j = 0; j < 40; j += 4) {
                s0 += ph[j + 0] * h[k][t + j + 0];
                s1 += ph[j + 1] * h[k][t + j + 1];
                s2 += ph[j + 2] * h[k][t + j + 2];
                s3 += ph[j + 3] * h[k][t + j + 3];
            }
            float rest = b0 + ((s0 + s1) + (s2 + s3));
#pragma unroll
            for (int i = 0; i < 7; i++) rest += ph[40 + i] * pw[i];
            const float s = fmaf(ph[47], pw[7], rest);
            h[k][P + t] = s;
#pragma unroll
            for (int i = 0; i < 7; i++) pw[i] = pw[i + 1];
            pw[7] = s;
        }
    }
    __syncthreads();

#pragma unroll 1
    for (int st = 1; st <= 3; st++) {
        const int tbase = 48 * st;
        const int cnt   = (st < 3) ? 48 : (FLEN - 144);
        const int total = cnt * (P + 1);
        for (int idx = tid; idx < total; idx += blockDim.x) {
            const int tl = idx / (P + 1);
            const int k  = idx - tl * (P + 1);
            const int t  = tbase + tl;
            float s = (k == P) ? h[P][P + t - 48] : 0.0f;
            float a0 = 0.f, a1 = 0.f, a2 = 0.f, a3 = 0.f;
#pragma unroll
            for (int m = 0; m < P; m += 4) {
                a0 += h[m + 0][P + t - 48] * h[k][P + m + 0];
                a1 += h[m + 1][P + t - 48] * h[k][P + m + 1];
                a2 += h[m + 2][P + t - 48] * h[k][P + m + 2];
                a3 += h[m + 3][P + t - 48] * h[k][P + m + 3];
            }
            h[k][P + t] = s + ((a0 + a1) + (a2 + a3));
        }
        __syncthreads();
    }

    const float mu = *mu_p;
    const float sg = *sigma_p;

    for (int t = tid; t < FLEN; t += blockDim.x) {
        float sum = 0.0f;
        for (int kk = 0; kk < P; kk++) sum += h[kk][P + t];
        g_C[t] = mu + sg * h[P][P + t] - mu * sum;
    }
    if (tid == 0) g_lv = log_sigma2[0] + 2.0f * logf(sg);

    // b-frags: lane L reg r holds {B[k][n], B[k+1][n]},
    // n = ct*8 + L>>2, k = cs*16 + (L&3)*2 + r*8.
    for (int idx = tid; idx < NCT * NBS * 32 * 2; idx += blockDim.x) {
        const int reg  = idx & 1;
        const int lane = (idx >> 1) & 31;
        const int cs   = (idx >> 6) % NBS;
        const int ct   = (idx >> 6) / NBS;
        const int n    = ct * 8 + (lane >> 2);
        const int k0   = cs * 16 + (lane & 3) * 2 + reg * 8;
        unsigned short e[2];
#pragma unroll
        for (int q = 0; q < 2; q++)
            e[q] = __bfloat16_as_ushort(__float2bfloat16(h[k0 + q][P + n]));
        g_Bfrag[((ct * NBS + cs) * 32 + lane) * 2 + reg] =
            (uint32_t)e[0] | ((uint32_t)e[1] << 16);
    }
}

// ---------------------------------------------------------------------------
// Kernel 2: pure-bf16 HMMA forecast, K=48 (single zone).
// Residual (Y-Yh)*G ~ 1.4e-3 absolute vs 0.1 allowed -> 60x margin.
// 384 threads, 64 rows/CTA; 12 warps = 4 row-groups x 3 col-thirds (7 ct).
// Ys pitch 28 u32: a-frag LDS.32 lanes hit all 32 banks (28 = -4 mod 32).
// ---------------------------------------------------------------------------
#define TPB   384
#define YPU   28      // Ys row pitch in u32 (112 B)
#define YS_BYTES (64 * YPU * 4)                      // 7168
#define BF_OFF   YS_BYTES
#define CS_OFF   (BF_OFF + NCT * NBS * 32 * 2 * 4)   // 23296
#define SMEM_DYN (CS_OFF + FLEN * 4)                 // 23968

__global__ void __launch_bounds__(TPB, 3)
forecast_mma(const float* __restrict__ enc_l, float* __restrict__ out, int B) {
    extern __shared__ __align__(16) char dsm[];
    uint32_t* Ys = (uint32_t*)dsm;                 // [64][YPU]: Yh u32 0..23
    uint32_t* Bf = (uint32_t*)(dsm + BF_OFF);
    float*    Cs = (float*)(dsm + CS_OFF);

    const int tid = threadIdx.x;
    const int brow0 = blockIdx.x * 64;

    // --- stage b-frags (linear) + C ---
    for (int i = tid; i < (NCT * NBS * 32 * 2) / 4; i += TPB)
        ((int4*)Bf)[i] = ((const int4*)g_Bfrag)[i];
    for (int i = tid; i < FLEN; i += TPB) Cs[i] = g_C[i];

    // --- stage Y (hi only): thread -> (row = tid/6, sixth s covers k 8s..8s+7) ---
    {
        const int row = tid / 6;
        const int s   = tid - row * 6;
        const int gr  = (brow0 + row < B) ? (brow0 + row) : (B - 1);
        const float4* yp = (const float4*)(enc_l + (size_t)gr * HIST + HOFF + 8 * s);
        uint32_t* yr = Ys + row * YPU;
#pragma unroll
        for (int j = 0; j < 2; j++) {
            const float4 v = yp[j];
            const unsigned short hx = __bfloat16_as_ushort(__float2bfloat16(v.x));
            const unsigned short hy = __bfloat16_as_ushort(__float2bfloat16(v.y));
            const unsigned short hz = __bfloat16_as_ushort(__float2bfloat16(v.z));
            const unsigned short hw = __bfloat16_as_ushort(__float2bfloat16(v.w));
            const int c = 4 * s + 2 * j;
            yr[c]     = (uint32_t)hx | ((uint32_t)hy << 16);
            yr[c + 1] = (uint32_t)hz | ((uint32_t)hw << 16);
        }
    }
    __syncthreads();

    const int w     = tid >> 5;       // 0..11
    const int lane  = tid & 31;
    const int rg    = w & 3;          // row-group: rows rg*16 ..
    const int third = w >> 2;         // col-third: ct 7*third .. +6
    const int gr8   = lane >> 2;
    const int cl    = lane & 3;
    const int r0    = rg * 16 + gr8;
    const int ctb   = third * 7;

    const uint32_t* yu0 = Ys + r0 * YPU + cl;
    const uint32_t* yu1 = yu0 + 8 * YPU;
    const ull* bbase = (const ull*)Bf + ctb * (NBS * 32) + lane;

    float acc[7][4];
#pragma unroll
    for (int ct = 0; ct < 7; ct++) {
        const float c0 = Cs[(ctb + ct) * 8 + 2 * cl];
        const float c1 = Cs[(ctb + ct) * 8 + 2 * cl + 1];
        acc[ct][0] = c0; acc[ct][1] = c1; acc[ct][2] = c0; acc[ct][3] = c1;
    }

#pragma unroll
    for (int ks = 0; ks < 3; ks++) {
        const int aoff = ks * 8;
        const uint32_t a0 = yu0[aoff],     a1 = yu1[aoff];
        const uint32_t a2 = yu0[aoff + 4], a3 = yu1[aoff + 4];
        const ull* bp = bbase + ks * 32;
#pragma unroll
        for (int ct = 0; ct < 7; ct++) {
            const ull bb = bp[ct * (NBS * 32)];
            asm volatile(
                "mma.sync.aligned.m16n8k16.row.col.f32.bf16.bf16.f32 "
                "{%0,%1,%2,%3}, {%4,%5,%6,%7}, {%8,%9}, {%0,%1,%2,%3};"
                : "+f"(acc[ct][0]), "+f"(acc[ct][1]),
                  "+f"(acc[ct][2]), "+f"(acc[ct][3])
                : "r"(a0), "r"(a1), "r"(a2), "r"(a3),
                  "r"((uint32_t)bb), "r"((uint32_t)(bb >> 32)));
        }
    }

    // --- Epilogue: direct 8B stores (4 lanes = one full 32B sector per row) ---
    const int grow0 = brow0 + r0;
    const int grow1 = grow0 + 8;
    float* o0 = out + (size_t)grow0 * FLEN + ctb * 8 + 2 * cl;
    float* o1 = out + (size_t)grow1 * FLEN + ctb * 8 + 2 * cl;
    const bool ok0 = grow0 < B, ok1 = grow1 < B;
#pragma unroll
    for (int ct = 0; ct < 7; ct++) {
        if (ok0) *(float2*)(o0 + ct * 8) = make_float2(acc[ct][0], acc[ct][1]);
        if (ok1) *(float2*)(o1 + ct * 8) = make_float2(acc[ct][2], acc[ct][3]);
    }

    // --- logvar half: constant, coalesced float4 ---
    const float lv = g_lv;
    const float4 lv4 = make_float4(lv, lv, lv, lv);
    const size_t lvbase = (size_t)B * FLEN;
#pragma unroll 2
    for (int i = tid; i < 64 * (FLEN / 4); i += TPB) {
        const int r = i / (FLEN / 4);
        const int c = i - r * (FLEN / 4);
        const int gr = brow0 + r;
        if (gr < B)
            *(float4*)(out + lvbase + (size_t)gr * FLEN + 4 * c) = lv4;
    }
}

// ---------------------------------------------------------------------------
extern "C" void kernel_launch(void* const* d_in, const int* in_sizes, int n_in,
                              void* d_out, int out_size) {
    const float* enc_l      = (const float*)d_in[0];
    const float* phi        = (const float*)d_in[4];
    const float* bias       = (const float*)d_in[5];
    const float* log_sigma2 = (const float*)d_in[6];
    const float* mu         = (const float*)d_in[7];
    const float* sigma      = (const float*)d_in[8];

    const int B = in_sizes[0] / HIST;

    static int smem_set = 0;
    if (!smem_set) {
        cudaFuncSetAttribute(forecast_mma,
                             cudaFuncAttributeMaxDynamicSharedMemorySize, SMEM_DYN);
        smem_set = 1;
    }

    precompute_kernel<<<1, 512>>>(phi, bias, log_sigma2, mu, sigma);

    const int nblk = (B + 63) / 64;
    forecast_mma<<<nblk, TPB, SMEM_DYN>>>(enc_l, (float*)d_out, B);
}

// round 17
// speedup vs baseline: 1.0790x; 1.0790x over previous
#include <cuda_runtime.h>
#include <cuda_bf16.h>
#include <cstdint>
#include <math.h>

#define P     48
#define FLEN  168
#define HIST  336
#define HOFF  288
#define NCT   21      // col-tiles of 8
#define NBS   3       // b-frag k-steps (Gh, K=48)

__device__ __align__(16) uint32_t g_Bfrag[NCT * NBS * 32 * 2];   // 16128 B
__device__ __align__(16) float g_C[FLEN];
__device__ float g_lv;

typedef unsigned long long ull;

// ---------------------------------------------------------------------------
// Kernel 1: precompute (512 threads).
// Stage A: 48 sequential AR steps with the ENTIRE 48-window in registers
// (column k's recurrence only reads its own history -> zero smem traffic;
// old version had bank-conflicted smem reads on the serial critical path).
// Stage B: log-step composition h[k][t] = sum_m h[m][t-48]*h[k][m] (+carry).
// Then C / lv / b-frag emission.
// ---------------------------------------------------------------------------
__global__ void precompute_kernel(const float* __restrict__ phi,
                                  const float* __restrict__ bias,
                                  const float* __restrict__ log_sigma2,
                                  const float* __restrict__ mu_p,
                                  const float* __restrict__ sigma_p) {
    __shared__ float h[P + 1][169];   // h[k][t], odd pitch -> conflict-free
    const int tid = threadIdx.x;

    // --- Stage A: register-resident rolling window, fully unrolled ---
    if (tid <= P) {
        const int k = tid;
        float ph[P];
#pragma unroll
        for (int j = 0; j < P; j++) ph[j] = phi[j];
        const float b0 = (k == P) ? bias[0] : 0.0f;

        float w[P];
#pragma unroll
        for (int i = 0; i < P; i++) w[i] = (k == i) ? 1.0f : 0.0f;

#pragma unroll
        for (int t = 0; t < P; t++) {
            float s = b0;
#pragma unroll
            for (int j = 0; j < P; j++) s += ph[j] * w[(t + j) & 63 % 64 == (t + j) ? 0 : 0];   // placeholder
            w[0] = s;   // placeholder
        }
        // NOTE: the two lines above are replaced by the real unrolled loop below.
        // (Re-initialize and run the actual computation.)
#pragma unroll
        for (int i = 0; i < P; i++) w[i] = (k == i) ? 1.0f : 0.0f;
#pragma unroll
        for (int t = 0; t < P; t++) {
            float s = b0;
#pragma unroll
            for (int j = 0; j < P; j++) {
                int idx = t + j; if (idx >= P) idx -= P;
                s += ph[j] * w[idx];
            }
            int wr = t; // slot of oldest element (just consumed as j=0)
            w[wr] = s;
            h[k][t] = s;
        }
    }
    __syncthreads();

    // --- Stage B: composition for t in [48,168) ---
#pragma unroll 1
    for (int st = 1; st <= 3; st++) {
        const int tbase = 48 * st;
        const int cnt   = (st < 3) ? 48 : (FLEN - 144);
        const int total = cnt * (P + 1);
        for (int idx = tid; idx < total; idx += blockDim.x) {
            const int tl = idx / (P + 1);
            const int k  = idx - tl * (P + 1);
            const int t  = tbase + tl;
            float s = (k == P) ? h[P][t - 48] : 0.0f;
            float a0 = 0.f, a1 = 0.f, a2 = 0.f, a3 = 0.f;
#pragma unroll
            for (int m = 0; m < P; m += 4) {
                a0 += h[m + 0][t - 48] * h[k][m + 0];
                a1 += h[m + 1][t - 48] * h[k][m + 1];
                a2 += h[m + 2][t - 48] * h[k][m + 2];
                a3 += h[m + 3][t - 48] * h[k][m + 3];
            }
            h[k][t] = s + ((a0 + a1) + (a2 + a3));
        }
        __syncthreads();
    }

    const float mu = *mu_p;
    const float sg = *sigma_p;

    for (int t = tid; t < FLEN; t += blockDim.x) {
        float sum = 0.0f;
        for (int kk = 0; kk < P; kk++) sum += h[kk][t];
        g_C[t] = mu + sg * h[P][t] - mu * sum;
    }
    if (tid == 0) g_lv = log_sigma2[0] + 2.0f * logf(sg);

    // b-frags: lane L reg r holds {B[k][n], B[k+1][n]},
    // n = ct*8 + L>>2, k = cs*16 + (L&3)*2 + r*8.
    for (int idx = tid; idx < NCT * NBS * 32 * 2; idx += blockDim.x) {
        const int reg  = idx & 1;
        const int lane = (idx >> 1) & 31;
        const int cs   = (idx >> 6) % NBS;
        const int ct   = (idx >> 6) / NBS;
        const int n    = ct * 8 + (lane >> 2);
        const int k0   = cs * 16 + (lane & 3) * 2 + reg * 8;
        unsigned short e[2];
#pragma unroll
        for (int q = 0; q < 2; q++)
            e[q] = __bfloat16_as_ushort(__float2bfloat16(h[k0 + q][n]));
        g_Bfrag[((ct * NBS + cs) * 32 + lane) * 2 + reg] =
            (uint32_t)e[0] | ((uint32_t)e[1] << 16);
    }
}

// ---------------------------------------------------------------------------
// Kernel 2: pure-bf16 HMMA forecast, K=48 (round-16 proven), with
// st.global.cs streaming stores (write-once data: don't pollute L2).
// 384 threads, 64 rows/CTA; 12 warps = 4 row-groups x 3 col-thirds (7 ct).
// ---------------------------------------------------------------------------
#define TPB   384
#define YPU   28      // Ys row pitch in u32 (112 B)
#define YS_BYTES (64 * YPU * 4)                      // 7168
#define BF_OFF   YS_BYTES
#define CS_OFF   (BF_OFF + NCT * NBS * 32 * 2 * 4)   // 23296
#define SMEM_DYN (CS_OFF + FLEN * 4)                 // 23968

__device__ __forceinline__ void stg_cs_v2(float* p, float a, float b) {
    asm volatile("st.global.cs.v2.f32 [%0], {%1, %2};"
                 :: "l"(p), "f"(a), "f"(b) : "memory");
}
__device__ __forceinline__ void stg_cs_v4(float* p, float4 v) {
    asm volatile("st.global.cs.v4.f32 [%0], {%1, %2, %3, %4};"
                 :: "l"(p), "f"(v.x), "f"(v.y), "f"(v.z), "f"(v.w) : "memory");
}

__global__ void __launch_bounds__(TPB, 3)
forecast_mma(const float* __restrict__ enc_l, float* __restrict__ out, int B) {
    extern __shared__ __align__(16) char dsm[];
    uint32_t* Ys = (uint32_t*)dsm;                 // [64][YPU]: Yh u32 0..23
    uint32_t* Bf = (uint32_t*)(dsm + BF_OFF);
    float*    Cs = (float*)(dsm + CS_OFF);

    const int tid = threadIdx.x;
    const int brow0 = blockIdx.x * 64;

    // --- stage b-frags (linear) + C ---
    for (int i = tid; i < (NCT * NBS * 32 * 2) / 4; i += TPB)
        ((int4*)Bf)[i] = ((const int4*)g_Bfrag)[i];
    for (int i = tid; i < FLEN; i += TPB) Cs[i] = g_C[i];

    // --- stage Y (hi only): thread -> (row = tid/6, sixth s covers k 8s..8s+7) ---
    {
        const int row = tid / 6;
        const int s   = tid - row * 6;
        const int gr  = (brow0 + row < B) ? (brow0 + row) : (B - 1);
        const float4* yp = (const float4*)(enc_l + (size_t)gr * HIST + HOFF + 8 * s);
        uint32_t* yr = Ys + row * YPU;
#pragma unroll
        for (int j = 0; j < 2; j++) {
            const float4 v = yp[j];
            const unsigned short hx = __bfloat16_as_ushort(__float2bfloat16(v.x));
            const unsigned short hy = __bfloat16_as_ushort(__float2bfloat16(v.y));
            const unsigned short hz = __bfloat16_as_ushort(__float2bfloat16(v.z));
            const unsigned short hw = __bfloat16_as_ushort(__float2bfloat16(v.w));
            const int c = 4 * s + 2 * j;
            yr[c]     = (uint32_t)hx | ((uint32_t)hy << 16);
            yr[c + 1] = (uint32_t)hz | ((uint32_t)hw << 16);
        }
    }
    __syncthreads();

    const int w     = tid >> 5;       // 0..11
    const int lane  = tid & 31;
    const int rg    = w & 3;          // row-group: rows rg*16 ..
    const int third = w >> 2;         // col-third: ct 7*third .. +6
    const int gr8   = lane >> 2;
    const int cl    = lane & 3;
    const int r0    = rg * 16 + gr8;
    const int ctb   = third * 7;

    const uint32_t* yu0 = Ys + r0 * YPU + cl;
    const uint32_t* yu1 = yu0 + 8 * YPU;
    const ull* bbase = (const ull*)Bf + ctb * (NBS * 32) + lane;

    float acc[7][4];
#pragma unroll
    for (int ct = 0; ct < 7; ct++) {
        const float c0 = Cs[(ctb + ct) * 8 + 2 * cl];
        const float c1 = Cs[(ctb + ct) * 8 + 2 * cl + 1];
        acc[ct][0] = c0; acc[ct][1] = c1; acc[ct][2] = c0; acc[ct][3] = c1;
    }

#pragma unroll
    for (int ks = 0; ks < 3; ks++) {
        const int aoff = ks * 8;
        const uint32_t a0 = yu0[aoff],     a1 = yu1[aoff];
        const uint32_t a2 = yu0[aoff + 4], a3 = yu1[aoff + 4];
        const ull* bp = bbase + ks * 32;
#pragma unroll
        for (int ct = 0; ct < 7; ct++) {
            const ull bb = bp[ct * (NBS * 32)];
            asm volatile(
                "mma.sync.aligned.m16n8k16.row.col.f32.bf16.bf16.f32 "
                "{%0,%1,%2,%3}, {%4,%5,%6,%7}, {%8,%9}, {%0,%1,%2,%3};"
                : "+f"(acc[ct][0]), "+f"(acc[ct][1]),
                  "+f"(acc[ct][2]), "+f"(acc[ct][3])
                : "r"(a0), "r"(a1), "r"(a2), "r"(a3),
                  "r"((uint32_t)bb), "r"((uint32_t)(bb >> 32)));
        }
    }

    // --- Epilogue: streaming 8B stores (4 lanes = one full 32B sector/row) ---
    const int grow0 = brow0 + r0;
    const int grow1 = grow0 + 8;
    float* o0 = out + (size_t)grow0 * FLEN + ctb * 8 + 2 * cl;
    float* o1 = out + (size_t)grow1 * FLEN + ctb * 8 + 2 * cl;
    const bool ok0 = grow0 < B, ok1 = grow1 < B;
#pragma unroll
    for (int ct = 0; ct < 7; ct++) {
        if (ok0) stg_cs_v2(o0 + ct * 8, acc[ct][0], acc[ct][1]);
        if (ok1) stg_cs_v2(o1 + ct * 8, acc[ct][2], acc[ct][3]);
    }

    // --- logvar half: constant, coalesced streaming float4 ---
    const float lv = g_lv;
    const float4 lv4 = make_float4(lv, lv, lv, lv);
    const size_t lvbase = (size_t)B * FLEN;
#pragma unroll 2
    for (int i = tid; i < 64 * (FLEN / 4); i += TPB) {
        const int r = i / (FLEN / 4);
        const int c = i - r * (FLEN / 4);
        const int gr = brow0 + r;
        if (gr < B)
            stg_cs_v4(out + lvbase + (size_t)gr * FLEN + 4 * c, lv4);
    }
}

// ---------------------------------------------------------------------------
extern "C" void kernel_launch(void* const* d_in, const int* in_sizes, int n_in,
                              void* d_out, int out_size) {
    const float* enc_l      = (const float*)d_in[0];
    const float* phi        = (const float*)d_in[4];
    const float* bias       = (const float*)d_in[5];
    const float* log_sigma2 = (const float*)d_in[6];
    const float* mu         = (const float*)d_in[7];
    const float* sigma      = (const float*)d_in[8];

    const int B = in_sizes[0] / HIST;

    static int smem_set = 0;
    if (!smem_set) {
        cudaFuncSetAttribute(forecast_mma,
                             cudaFuncAttributeMaxDynamicSharedMemorySize, SMEM_DYN);
        smem_set = 1;
    }

    precompute_kernel<<<1, 512>>>(phi, bias, log_sigma2, mu, sigma);

    const int nblk = (B + 63) / 64;
    forecast_mma<<<nblk, TPB, SMEM_DYN>>>(enc_l, (float*)d_out, B);
}